// round 5
// baseline (speedup 1.0000x reference)
#include <cuda_runtime.h>
#include <cstdint>

// Problem constants
#define NB      16
#define CDIM    64
#define HWDIM   4096          // 64*64
#define NTOT    65536         // NB*HWDIM
#define KCB     512           // n_embeddings
#define OUT_Q   4194304       // NB*CDIM*HWDIM
// out layout (all f32): [quantized OUT_Q][loss][perplexity][active][indices NTOT]
#define OFF_LOSS (OUT_Q)
#define OFF_PERP (OUT_Q + 1)
#define OFF_ACT  (OUT_Q + 2)
#define OFF_IDX  (OUT_Q + 3)

#define TPB     512
#define GRID    148           // persistent: one block per SM
#define TILE    64            // points per tile
#define NTILES  (NTOT / TILE) // 1024 -> 6.92 tiles/block, ceil 7 => 0.988 balance

// dynamic smem layout (float indices)
#define SF_E     0                       // swizzled codebook: 512*64
#define SF_X     (SF_E + KCB * CDIM)     // x tile, [64][68] padded
#define SF_NORM  (SF_X + TILE * 68)      // padded norms: 520
#define SF_HIST  (SF_NORM + 520)         // uint hist: 512
#define SF_BESTK (SF_HIST + KCB)         // int: 64
#define SMEM_FLOATS (SF_BESTK + TILE)
#define SMEM_BYTES  (SMEM_FLOATS * 4)    // ~152.9 KB -> 1 block/SM

// Accumulators: zero at module load (.bss); vq_finalize re-zeroes them after
// use so every graph replay starts from zero.
__device__ float        g_loss;
__device__ unsigned int g_hist[KCB];

extern __shared__ float s_dyn[];

__global__ __launch_bounds__(TPB, 1)
void vq_main(const float* __restrict__ x,
             const float* __restrict__ E,
             float* __restrict__ out) {
    float*        sE    = s_dyn + SF_E;
    float*        sx    = s_dyn + SF_X;
    float*        snorm = s_dyn + SF_NORM;
    unsigned int* shist = (unsigned int*)(s_dyn + SF_HIST);
    int*          sbk   = (int*)(s_dyn + SF_BESTK);
    __shared__ float s_warpsum[16];

    const int tid = threadIdx.x;
    float4* sE4 = reinterpret_cast<float4*>(sE);

    // ---- stage codebook once, chunk-swizzled: chunk i of row k stored at
    //      float4 slot k*16 + ((i + (k>>6)) & 15)
    {
        const float4* Eg = reinterpret_cast<const float4*>(E);
#pragma unroll
        for (int f = tid; f < KCB * CDIM / 4; f += TPB) {
            int k = f >> 4, i = f & 15;
            sE4[(k << 4) + ((i + (k >> 6)) & 15)] = Eg[f];
        }
        shist[tid] = 0u;
    }
    __syncthreads();

    // ---- row norms from smem (rotated visit order -> <=4-way conflicts)
    {
        int k = tid;
        const float4* row = sE4 + (k << 4);
        float s = 0.f;
#pragma unroll
        for (int s0 = 0; s0 < 16; s0++) {
            float4 v = row[(s0 + k) & 15];
            s = fmaf(v.x, v.x, s);
            s = fmaf(v.y, v.y, s);
            s = fmaf(v.z, v.z, s);
            s = fmaf(v.w, v.w, s);
        }
        snorm[k + (k >> 6)] = s;      // padded index: lanes k, k+64.. -> distinct banks
    }
    __syncthreads();

    const int p  = tid >> 3;          // point within tile (0..63)
    const int q  = tid & 7;           // code slice (0..7) -> k in [64q, 64q+64)
    const int pw = tid & 63;          // write-phase point id
    const int cg = tid >> 6;          // write-phase channel group (0..7)

    float loss_acc = 0.f;

    for (int t = blockIdx.x; t < NTILES; t += GRID) {
        const int nb  = t << 6;
        const int b   = nb >> 12;
        const int hwb = nb & (HWDIM - 1);
        const float* xg = x + (size_t)b * CDIM * HWDIM + hwb;

        // ---- stage x tile: sx[p][c], stride 68 (coalesced gmem, ok smem)
#pragma unroll
        for (int j = 0; j < 8; j++) {
            int c = cg + (j << 3);
            sx[pw * 68 + c] = xg[(size_t)c * HWDIM + pw];
        }
        __syncthreads();

        // ---- pull own row into registers (float4, multicast LDS) + xnorm
        float xr[CDIM];
        float xnorm = 0.f;
        {
            const float4* sxp = reinterpret_cast<const float4*>(sx + p * 68);
#pragma unroll
            for (int i = 0; i < 16; i++) {
                float4 v = sxp[i];
                xr[4*i+0] = v.x; xr[4*i+1] = v.y;
                xr[4*i+2] = v.z; xr[4*i+3] = v.w;
                xnorm = fmaf(v.x, v.x, xnorm);
                xnorm = fmaf(v.y, v.y, xnorm);
                xnorm = fmaf(v.z, v.z, xnorm);
                xnorm = fmaf(v.w, v.w, xnorm);
            }
        }

        // ---- argmin over this thread's 64 codes (exact R1 accumulation order)
        float bestd = 3.4e38f;
        int   bestk = 0;
        const float4* qbase = sE4 + (q << 10);       // rows 64q.. : q*64*16 float4
#pragma unroll 2
        for (int kk = 0; kk < 64; kk++) {
            const float4* r4 = qbase + (kk << 4);
            float a0 = 0.f, a1 = 0.f, a2 = 0.f, a3 = 0.f;
#pragma unroll
            for (int i = 0; i < 16; i++) {
                float4 ev = r4[(i + q) & 15];        // swizzled slot, real chunk i
                a0 = fmaf(xr[4*i+0], ev.x, a0);
                a1 = fmaf(xr[4*i+1], ev.y, a1);
                a2 = fmaf(xr[4*i+2], ev.z, a2);
                a3 = fmaf(xr[4*i+3], ev.w, a3);
            }
            float dot  = (a0 + a1) + (a2 + a3);
            int   k    = (q << 6) + kk;
            float dist = fmaf(-2.f, dot, snorm[k + q]);
            if (dist < bestd) { bestd = dist; bestk = k; }  // strict <: first wins
        }

        // ---- merge the 8 partial argmins (lowest dist, ties -> lowest k)
#pragma unroll
        for (int off = 1; off < 8; off <<= 1) {
            float od = __shfl_xor_sync(0xFFFFFFFFu, bestd, off);
            int   ok = __shfl_xor_sync(0xFFFFFFFFu, bestk, off);
            if (od < bestd || (od == bestd && ok < bestk)) { bestd = od; bestk = ok; }
        }
        if (q == 0) {
            loss_acc += bestd + xnorm;   // ||x - e_best||^2
            sbk[p] = bestk;
            atomicAdd(&shist[bestk], 1u);
        }
        __syncthreads();

        // ---- cooperative coalesced writes: quantized + indices
        {
            float* op = out + (size_t)b * CDIM * HWDIM + hwb;
            int bk  = sbk[pw];
            int qq  = bk >> 6;
            const float* erow = sE + (bk << 6);
#pragma unroll
            for (int j = 0; j < 8; j++) {
                int c   = cg + (j << 3);
                int pos = ((c >> 2) + qq) & 15;              // de-swizzle
                float v = erow[(pos << 2) + (c & 3)];
                op[(size_t)c * HWDIM + pw] = v;
            }
            if (tid < TILE) out[OFF_IDX + nb + tid] = (float)sbk[tid];
        }
        __syncthreads();
    }

    // ---- block reductions -> globals
#pragma unroll
    for (int off = 16; off; off >>= 1)
        loss_acc += __shfl_xor_sync(0xFFFFFFFFu, loss_acc, off);
    if ((tid & 31) == 0) s_warpsum[tid >> 5] = loss_acc;
    __syncthreads();

    atomicAdd(&g_hist[tid], shist[tid]);
    if (tid == 0) {
        float bsum = 0.f;
#pragma unroll
        for (int i = 0; i < 16; i++) bsum += s_warpsum[i];
        atomicAdd(&g_loss, bsum);
    }
}

// ---------------------------------------------------------------------------
// finalize: perplexity + loss + active_codes scalars; then re-zero the
// accumulators so the next graph replay starts clean.
// ---------------------------------------------------------------------------
__global__ void vq_finalize(const float* __restrict__ w, float* __restrict__ out) {
    __shared__ float s_ent[16];
    __shared__ float s_act[16];
    int t = threadIdx.x;                        // 512 threads, one code each

    float pr  = (float)g_hist[t] * (1.0f / (float)NTOT);
    float ent = pr * logf(pr + 1e-10f);
    float act = (w[t] >= 0.01f) ? 1.f : 0.f;

#pragma unroll
    for (int off = 16; off; off >>= 1) {
        ent += __shfl_xor_sync(0xFFFFFFFFu, ent, off);
        act += __shfl_xor_sync(0xFFFFFFFFu, act, off);
    }
    if ((t & 31) == 0) { s_ent[t >> 5] = ent; s_act[t >> 5] = act; }
    __syncthreads();
    if (t == 0) {
        float esum = 0.f, asum = 0.f;
#pragma unroll
        for (int i = 0; i < 16; i++) { esum += s_ent[i]; asum += s_act[i]; }
        out[OFF_LOSS] = g_loss * (1.0f / ((float)NTOT * (float)CDIM));
        out[OFF_PERP] = expf(-esum);
        out[OFF_ACT]  = asum;
    }
    __syncthreads();
    g_hist[t] = 0u;                             // reset for next replay
    if (t == 0) g_loss = 0.f;
}

// ---------------------------------------------------------------------------
extern "C" void kernel_launch(void* const* d_in, const int* in_sizes, int n_in,
                              void* d_out, int out_size) {
    const float* x = (const float*)d_in[0];   // [16,64,64,64]
    const float* E = (const float*)d_in[1];   // [512,64]
    const float* w = (const float*)d_in[2];   // [512]
    float* out = (float*)d_out;

    cudaFuncSetAttribute(vq_main, cudaFuncAttributeMaxDynamicSharedMemorySize,
                         SMEM_BYTES);

    vq_main<<<GRID, TPB, SMEM_BYTES>>>(x, E, out);
    vq_finalize<<<1, KCB>>>(w, out);
}

// round 6
// speedup vs baseline: 1.5908x; 1.5908x over previous
#include <cuda_runtime.h>
#include <cstdint>

// Problem constants
#define NB      16
#define CDIM    64
#define HWDIM   4096          // 64*64
#define NTOT    65536         // NB*HWDIM
#define KCB     512           // n_embeddings
#define OUT_Q   4194304       // NB*CDIM*HWDIM
// out layout (all f32): [quantized OUT_Q][loss][perplexity][active][indices NTOT]
#define OFF_LOSS (OUT_Q)
#define OFF_PERP (OUT_Q + 1)
#define OFF_ACT  (OUT_Q + 2)
#define OFF_IDX  (OUT_Q + 3)

#define TPB     512
#define GRID    148           // persistent: one block per SM
#define TILE    64            // points per tile
#define NTILES  (NTOT / TILE) // 1024 -> 6.92/block, ceil 7 -> 0.988 balance

// dynamic smem layout (float indices) — codebook LINEAR, no swizzle
#define SF_E     0                       // 512*64                = 32768
#define SF_X     (SF_E + KCB * CDIM)     // x tile [c][p] 64*64   =  4096
#define SF_NORM  (SF_X + CDIM * TILE)    // 512
#define SF_SD    (SF_NORM + KCB)         // partial dists [q][p]  = 512
#define SF_SK    (SF_SD + 8 * TILE)      // partial ks    [q][p]  = 512
#define SF_HIST  (SF_SK + 8 * TILE)      // 512
#define SF_BESTK (SF_HIST + KCB)         // 64
#define SMEM_FLOATS (SF_BESTK + TILE)
#define SMEM_BYTES  (SMEM_FLOATS * 4)    // 155,904 B -> 1 block/SM

// Accumulators: zero at module load (.bss); vq_finalize re-zeroes after use.
__device__ float        g_loss;
__device__ unsigned int g_hist[KCB];

extern __shared__ float s_dyn[];

__global__ __launch_bounds__(TPB, 1)
void vq_main(const float* __restrict__ x,
             const float* __restrict__ E,
             float* __restrict__ out) {
    float*        sE    = s_dyn + SF_E;
    float*        sx    = s_dyn + SF_X;
    float*        snorm = s_dyn + SF_NORM;
    float*        sd    = s_dyn + SF_SD;
    int*          sk    = (int*)(s_dyn + SF_SK);
    unsigned int* shist = (unsigned int*)(s_dyn + SF_HIST);
    int*          sbk   = (int*)(s_dyn + SF_BESTK);
    __shared__ float s_warpsum[16];

    const int tid = threadIdx.x;
    float4* sE4 = reinterpret_cast<float4*>(sE);

    // ---- stage codebook once (linear, coalesced)
    {
        const float4* Eg = reinterpret_cast<const float4*>(E);
#pragma unroll
        for (int f = tid; f < KCB * CDIM / 4; f += TPB) sE4[f] = Eg[f];
        shist[tid] = 0u;
    }
    __syncthreads();

    // ---- row norms from smem (rotated visit -> bounded conflicts; once)
    {
        const float4* row = sE4 + (tid << 4);
        float s = 0.f;
#pragma unroll
        for (int s0 = 0; s0 < 16; s0++) {
            float4 v = row[(s0 + tid) & 15];
            s = fmaf(v.x, v.x, s);
            s = fmaf(v.y, v.y, s);
            s = fmaf(v.z, v.z, s);
            s = fmaf(v.w, v.w, s);
        }
        snorm[tid] = s;
    }
    __syncthreads();

    const int w    = tid >> 5;        // warp 0..15
    const int lane = tid & 31;
    const int q    = w & 7;           // code slice: [64q, 64q+64)
    const int hi   = w >> 3;          // point half (0/1)
    const int p    = (hi << 5) + lane;// this thread's point within tile
    const int pw   = tid & 63;        // staging/writeout point id
    const int cg   = tid >> 6;        // staging/writeout channel group (0..7)

    float loss_acc = 0.f;             // Σ bestd   (merge threads only)
    float xsq_acc  = 0.f;             // Σ x^2     (staging threads)

    for (int t = blockIdx.x; t < NTILES; t += GRID) {
        const int nb  = t << 6;
        const int b   = nb >> 12;
        const int hwb = nb & (HWDIM - 1);
        const float* xg = x + (size_t)b * CDIM * HWDIM + hwb;

        // ---- stage x tile channel-major sx[c][p] (coalesced gmem, cf smem)
#pragma unroll
        for (int j = 0; j < 8; j++) {
            int c = (cg << 3) + j;
            float v = xg[(size_t)c * HWDIM + pw];
            sx[(c << 6) + pw] = v;
            xsq_acc = fmaf(v, v, xsq_acc);
        }
        __syncthreads();

        // ---- pull own point's row into registers (conflict-free scalar LDS)
        float xr[CDIM];
#pragma unroll
        for (int c = 0; c < CDIM; c++) xr[c] = sx[(c << 6) + p];

        // ---- argmin over this warp's 64 codes — R1's exact inner loop:
        //      broadcast LDS.128, immediate offsets, 4 accumulators
        float bestd = 3.4e38f;
        int   bestk = 0;
        const int kbase = q << 6;
        const float4* qrow = sE4 + ((size_t)kbase << 4);
#pragma unroll 2
        for (int kk = 0; kk < 64; kk++) {
            const float4* r4 = qrow + (kk << 4);
            float a0 = 0.f, a1 = 0.f, a2 = 0.f, a3 = 0.f;
#pragma unroll
            for (int i = 0; i < 16; i++) {
                float4 ev = r4[i];                 // broadcast, imm offset
                a0 = fmaf(xr[4*i+0], ev.x, a0);
                a1 = fmaf(xr[4*i+1], ev.y, a1);
                a2 = fmaf(xr[4*i+2], ev.z, a2);
                a3 = fmaf(xr[4*i+3], ev.w, a3);
            }
            float dot  = (a0 + a1) + (a2 + a3);
            float dist = fmaf(-2.f, dot, snorm[kbase + kk]);
            if (dist < bestd) { bestd = dist; bestk = kbase + kk; }
        }
        sd[(q << 6) + p] = bestd;
        sk[(q << 6) + p] = bestk;
        __syncthreads();

        // ---- merge 8 slice-partials per point (tid<64); ascending q keeps
        //      lowest k on exact ties (slices are ascending k-ranges)
        if (tid < TILE) {
            float bd = sd[tid];
            int   bk = sk[tid];
#pragma unroll
            for (int qq = 1; qq < 8; qq++) {
                float d2 = sd[(qq << 6) + tid];
                int   k2 = sk[(qq << 6) + tid];
                if (d2 < bd) { bd = d2; bk = k2; }
            }
            loss_acc += bd;                       // + ||x||^2 added globally
            sbk[tid] = bk;
            atomicAdd(&shist[bk], 1u);
            out[OFF_IDX + nb + tid] = (float)bk;
        }
        __syncthreads();

        // ---- cooperative coalesced writeout of quantized rows
        {
            float* op = out + (size_t)b * CDIM * HWDIM + hwb;
            int bk = sbk[pw];
            const float4* er = reinterpret_cast<const float4*>(E + (bk << 6));
            float4 v0 = er[(cg << 1) + 0];        // channels 8cg..8cg+3 (L1/L2)
            float4 v1 = er[(cg << 1) + 1];        // channels 8cg+4..8cg+7
            float vv[8] = {v0.x, v0.y, v0.z, v0.w, v1.x, v1.y, v1.z, v1.w};
#pragma unroll
            for (int j = 0; j < 8; j++) {
                int c = (cg << 3) + j;            // cg const per warp -> coalesced
                op[(size_t)c * HWDIM + pw] = vv[j];
            }
        }
        __syncthreads();
    }

    // ---- block reduction: loss = Σ bestd + Σ x^2
    float tot = loss_acc + xsq_acc;
#pragma unroll
    for (int off = 16; off; off >>= 1)
        tot += __shfl_xor_sync(0xFFFFFFFFu, tot, off);
    if (lane == 0) s_warpsum[w] = tot;
    __syncthreads();

    atomicAdd(&g_hist[tid], shist[tid]);
    if (tid == 0) {
        float bsum = 0.f;
#pragma unroll
        for (int i = 0; i < 16; i++) bsum += s_warpsum[i];
        atomicAdd(&g_loss, bsum);
    }
}

// ---------------------------------------------------------------------------
// finalize: perplexity + loss + active_codes; re-zero accumulators for the
// next graph replay.
// ---------------------------------------------------------------------------
__global__ void vq_finalize(const float* __restrict__ w, float* __restrict__ out) {
    __shared__ float s_ent[16];
    __shared__ float s_act[16];
    int t = threadIdx.x;                        // 512 threads, one code each

    float pr  = (float)g_hist[t] * (1.0f / (float)NTOT);
    float ent = pr * logf(pr + 1e-10f);
    float act = (w[t] >= 0.01f) ? 1.f : 0.f;

#pragma unroll
    for (int off = 16; off; off >>= 1) {
        ent += __shfl_xor_sync(0xFFFFFFFFu, ent, off);
        act += __shfl_xor_sync(0xFFFFFFFFu, act, off);
    }
    if ((t & 31) == 0) { s_ent[t >> 5] = ent; s_act[t >> 5] = act; }
    __syncthreads();
    if (t == 0) {
        float esum = 0.f, asum = 0.f;
#pragma unroll
        for (int i = 0; i < 16; i++) { esum += s_ent[i]; asum += s_act[i]; }
        out[OFF_LOSS] = g_loss * (1.0f / ((float)NTOT * (float)CDIM));
        out[OFF_PERP] = expf(-esum);
        out[OFF_ACT]  = asum;
    }
    __syncthreads();
    g_hist[t] = 0u;                             // reset for next replay
    if (t == 0) g_loss = 0.f;
}

// ---------------------------------------------------------------------------
extern "C" void kernel_launch(void* const* d_in, const int* in_sizes, int n_in,
                              void* d_out, int out_size) {
    const float* x = (const float*)d_in[0];   // [16,64,64,64]
    const float* E = (const float*)d_in[1];   // [512,64]
    const float* w = (const float*)d_in[2];   // [512]
    float* out = (float*)d_out;

    cudaFuncSetAttribute(vq_main, cudaFuncAttributeMaxDynamicSharedMemorySize,
                         SMEM_BYTES);

    vq_main<<<GRID, TPB, SMEM_BYTES>>>(x, E, out);
    vq_finalize<<<1, KCB>>>(w, out);
}

// round 8
// speedup vs baseline: 2.6861x; 1.6885x over previous
#include <cuda_runtime.h>
#include <cuda_bf16.h>
#include <cstdint>

// Problem constants
#define NB      16
#define CDIM    64
#define HWDIM   4096
#define NTOT    65536
#define KCB     512
#define OUT_Q   4194304
#define OFF_LOSS (OUT_Q)
#define OFF_PERP (OUT_Q + 1)
#define OFF_ACT  (OUT_Q + 2)
#define OFF_IDX  (OUT_Q + 3)

#define TPB     512
#define GRID    148
#define TILEP   64
#define NTILES  (NTOT / TILEP)      // 1024 -> 6.92/CTA -> 0.988 balance

// smem rows padded to 72 halves (144B = 36 banks) -> ldmatrix conflict-free
#define ROWB    144
// ---- dynamic smem byte offsets (16B aligned) ----
#define SO_BHI   0                  // E_hi bf16 [512][72h]  = 73728
#define SO_BLO   73728              // E_lo                  = 73728
#define SO_AHI   147456             // X_hi bf16 [64][72h]   =  9216
#define SO_ALO   156672             // X_lo                  =  9216
#define SO_SNORM 165888             // 512 f
#define SO_H     167936             // 512 f (= norm/2)
#define SO_SD    169984             // float [64][4][3]      =  3072
#define SO_SI    173056             // int   [64][4][3]      =  3072
#define SO_HIST  176128             // 512 u32
#define SO_SBK   178176             // 64 int
#define SO_WSUM  178432             // 16 f
#define SMEM_BYTES 178496

__device__ float        g_loss;
__device__ unsigned int g_hist[KCB];

// ---------------- family-portable tensor helpers (sm_80+ PTX only) --------
__device__ __forceinline__ void mma16816(float* d, const uint32_t* a,
                                         const uint32_t* b) {
    asm volatile(
        "mma.sync.aligned.m16n8k16.row.col.f32.bf16.bf16.f32 "
        "{%0,%1,%2,%3}, {%4,%5,%6,%7}, {%8,%9}, {%0,%1,%2,%3};"
        : "+f"(d[0]), "+f"(d[1]), "+f"(d[2]), "+f"(d[3])
        : "r"(a[0]), "r"(a[1]), "r"(a[2]), "r"(a[3]), "r"(b[0]), "r"(b[1]));
}
__device__ __forceinline__ void ldsm4(uint32_t* r, uint32_t addr) {
    asm volatile("ldmatrix.sync.aligned.m8n8.x4.shared.b16 {%0,%1,%2,%3}, [%4];"
                 : "=r"(r[0]), "=r"(r[1]), "=r"(r[2]), "=r"(r[3]) : "r"(addr));
}
__device__ __forceinline__ void ldsm2(uint32_t* r, uint32_t addr) {
    asm volatile("ldmatrix.sync.aligned.m8n8.x2.shared.b16 {%0,%1}, [%2];"
                 : "=r"(r[0]), "=r"(r[1]) : "r"(addr));
}
__device__ __forceinline__ void pack_hilo(float f0, float f1,
                                          uint32_t& whi, uint32_t& wlo) {
    __nv_bfloat16 h0 = __float2bfloat16_rn(f0);
    __nv_bfloat16 h1 = __float2bfloat16_rn(f1);
    float r0 = f0 - __bfloat162float(h0);
    float r1 = f1 - __bfloat162float(h1);
    __nv_bfloat16 l0 = __float2bfloat16_rn(r0);
    __nv_bfloat16 l1 = __float2bfloat16_rn(r1);
    whi = (uint32_t)__bfloat16_as_ushort(h0) | ((uint32_t)__bfloat16_as_ushort(h1) << 16);
    wlo = (uint32_t)__bfloat16_as_ushort(l0) | ((uint32_t)__bfloat16_as_ushort(l1) << 16);
}
__device__ __forceinline__ void top3_upd(float m, int k,
                                         float& b1, float& b2, float& b3,
                                         int& k1, int& k2, int& k3) {
    if (m > b3) {
        if (m > b2) {
            b3 = b2; k3 = k2;
            if (m > b1) { b2 = b1; k2 = k1; b1 = m; k1 = k; }
            else        { b2 = m;  k2 = k; }
        } else { b3 = m; k3 = k; }
    }
}

// ---------------------------------------------------------------------------
extern __shared__ char sm[];

__global__ __launch_bounds__(TPB, 1)
void vq_main(const float* __restrict__ x,
             const float* __restrict__ E,
             float* __restrict__ out) {
    float*        snorm = (float*)(sm + SO_SNORM);
    float*        hh    = (float*)(sm + SO_H);
    float*        sd    = (float*)(sm + SO_SD);
    int*          si    = (int*)(sm + SO_SI);
    unsigned int* shist = (unsigned int*)(sm + SO_HIST);
    int*          sbk   = (int*)(sm + SO_SBK);
    float*        wsum  = (float*)(sm + SO_WSUM);

    const int tid  = threadIdx.x;
    const int wid  = tid >> 5;
    const int lane = tid & 31;

    // ---- one-time: codebook -> bf16 hi/lo (padded rows) + norms
    {
        const int k = tid;
        const float4* er = reinterpret_cast<const float4*>(E + (k << 6));
        char* bh = sm + SO_BHI + k * ROWB;
        char* bl = sm + SO_BLO + k * ROWB;
        float s = 0.f;
#pragma unroll
        for (int i = 0; i < 16; i++) {
            float4 v = er[i];
            s = fmaf(v.x, v.x, s); s = fmaf(v.y, v.y, s);
            s = fmaf(v.z, v.z, s); s = fmaf(v.w, v.w, s);
            uint32_t whi, wlo;
            pack_hilo(v.x, v.y, whi, wlo);
            *(uint32_t*)(bh + i * 8)     = whi;
            *(uint32_t*)(bl + i * 8)     = wlo;
            pack_hilo(v.z, v.w, whi, wlo);
            *(uint32_t*)(bh + i * 8 + 4) = whi;
            *(uint32_t*)(bl + i * 8 + 4) = wlo;
        }
        snorm[k] = s;
        hh[k]    = 0.5f * s;
        shist[k] = 0u;
    }
    __syncthreads();

    const int pw  = tid & 63;     // staging/writeout point
    const int cgi = tid >> 6;     // staging/writeout channel group (0..7)
    const int rg  = wid >> 2;     // row group: points rg*16 .. +15
    const int wq  = wid & 3;      // code quarter: codes wq*128 .. +127

    // ldmatrix lane addressing (precomputed)
    const uint32_t smu = (uint32_t)__cvta_generic_to_shared(sm);
    const int sel = lane >> 3;                       // x4 matrix id 0..3
    const uint32_t aoff =
        (uint32_t)(rg * 16 + (lane & 7) + (sel & 1) * 8) * ROWB + (uint32_t)((sel >> 1) * 16);
    const uint32_t ahiA = smu + SO_AHI + aoff;
    const uint32_t aloA = smu + SO_ALO + aoff;
    const uint32_t bln  = (uint32_t)((lane & 7) * ROWB + ((lane >> 3) & 1) * 16);
    const uint32_t bhiB = smu + SO_BHI + bln;
    const uint32_t bloB = smu + SO_BLO + bln;

    float loss_acc = 0.f, xsq_acc = 0.f;

    for (int t = blockIdx.x; t < NTILES; t += GRID) {
        const int nb  = t << 6;
        const int b   = nb >> 12;
        const int hwb = nb & (HWDIM - 1);
        const float* xg = x + (size_t)b * CDIM * HWDIM + hwb;

        // ---- stage X tile: bf16 hi/lo, padded rows (coalesced gmem reads)
#pragma unroll
        for (int jj = 0; jj < 4; jj++) {
            int c0 = (cgi << 3) + (jj << 1);
            float v0 = xg[(size_t)c0 * HWDIM + pw];
            float v1 = xg[(size_t)(c0 + 1) * HWDIM + pw];
            xsq_acc = fmaf(v0, v0, xsq_acc);
            xsq_acc = fmaf(v1, v1, xsq_acc);
            uint32_t whi, wlo;
            pack_hilo(v0, v1, whi, wlo);
            *(uint32_t*)(sm + SO_AHI + pw * ROWB + c0 * 2) = whi;
            *(uint32_t*)(sm + SO_ALO + pw * ROWB + c0 * 2) = wlo;
        }
        __syncthreads();

        // ---- load A fragments (persist across the n-loop)
        uint32_t ahi[16], alo[16];
#pragma unroll
        for (int kt = 0; kt < 4; kt++) {
            ldsm4(ahi + 4 * kt, ahiA + kt * 32);
            ldsm4(alo + 4 * kt, aloA + kt * 32);
        }

        // ---- per-lane top-3 (maximize m = dot - ||e||^2/2), rows g and g+8
        float a1 = -3.4e38f, a2 = -3.4e38f, a3 = -3.4e38f;
        float c1 = -3.4e38f, c2 = -3.4e38f, c3 = -3.4e38f;
        int ka1 = 0, ka2 = 0, ka3 = 0, kc1 = 0, kc2 = 0, kc3 = 0;

        const uint32_t nqbase = (uint32_t)(wq * 128) * ROWB;
#pragma unroll 2
        for (int nt = 0; nt < 16; nt++) {
            const uint32_t nbyt = nqbase + (uint32_t)(nt * 8) * ROWB;
            float acc[4] = {0.f, 0.f, 0.f, 0.f};
            float ac2[4] = {0.f, 0.f, 0.f, 0.f};
#pragma unroll
            for (int kt = 0; kt < 4; kt++) {
                uint32_t bh[2], bl[2];
                ldsm2(bh, bhiB + nbyt + kt * 32);
                ldsm2(bl, bloB + nbyt + kt * 32);
                mma16816(acc, ahi + 4 * kt, bh);   // hi*hi
                mma16816(ac2, alo + 4 * kt, bh);   // lo*hi
                mma16816(acc, ahi + 4 * kt, bl);   // hi*lo
            }
            const int c0 = wq * 128 + nt * 8 + 2 * (lane & 3);
            float2 hp = *(const float2*)(hh + c0);
            top3_upd(acc[0] + ac2[0] - hp.x, c0,     a1, a2, a3, ka1, ka2, ka3);
            top3_upd(acc[1] + ac2[1] - hp.y, c0 + 1, a1, a2, a3, ka1, ka2, ka3);
            top3_upd(acc[2] + ac2[2] - hp.x, c0,     c1, c2, c3, kc1, kc2, kc3);
            top3_upd(acc[3] + ac2[3] - hp.y, c0 + 1, c1, c2, c3, kc1, kc2, kc3);
        }

        // ---- merge across the 4 lanes sharing each row (bfly 1,2)
#pragma unroll
        for (int off = 1; off <= 2; off <<= 1) {
            float o1 = __shfl_xor_sync(0xFFFFFFFFu, a1, off);
            float o2 = __shfl_xor_sync(0xFFFFFFFFu, a2, off);
            float o3 = __shfl_xor_sync(0xFFFFFFFFu, a3, off);
            int   p1 = __shfl_xor_sync(0xFFFFFFFFu, ka1, off);
            int   p2 = __shfl_xor_sync(0xFFFFFFFFu, ka2, off);
            int   p3 = __shfl_xor_sync(0xFFFFFFFFu, ka3, off);
            top3_upd(o1, p1, a1, a2, a3, ka1, ka2, ka3);
            top3_upd(o2, p2, a1, a2, a3, ka1, ka2, ka3);
            top3_upd(o3, p3, a1, a2, a3, ka1, ka2, ka3);
            o1 = __shfl_xor_sync(0xFFFFFFFFu, c1, off);
            o2 = __shfl_xor_sync(0xFFFFFFFFu, c2, off);
            o3 = __shfl_xor_sync(0xFFFFFFFFu, c3, off);
            p1 = __shfl_xor_sync(0xFFFFFFFFu, kc1, off);
            p2 = __shfl_xor_sync(0xFFFFFFFFu, kc2, off);
            p3 = __shfl_xor_sync(0xFFFFFFFFu, kc3, off);
            top3_upd(o1, p1, c1, c2, c3, kc1, kc2, kc3);
            top3_upd(o2, p2, c1, c2, c3, kc1, kc2, kc3);
            top3_upd(o3, p3, c1, c2, c3, kc1, kc2, kc3);
        }
        if ((lane & 3) == 0) {
            int ra = rg * 16 + (lane >> 2);
            int rb = ra + 8;
            int ba = (ra * 4 + wq) * 3;
            int bb = (rb * 4 + wq) * 3;
            sd[ba] = a1; sd[ba + 1] = a2; sd[ba + 2] = a3;
            si[ba] = ka1; si[ba + 1] = ka2; si[ba + 2] = ka3;
            sd[bb] = c1; sd[bb + 1] = c2; sd[bb + 2] = c3;
            si[bb] = kc1; si[bb + 1] = kc2; si[bb + 2] = kc3;
        }
        __syncthreads();

        // ---- merge 12 candidates -> top3 -> EXACT fp32 rescore (R1 formula)
        if (tid < TILEP) {
            const int p = tid;
            float m1 = -3.4e38f, m2 = -3.4e38f, m3 = -3.4e38f;
            int   i1 = 0, i2 = 0, i3 = 0;
#pragma unroll
            for (int qq = 0; qq < 4; qq++) {
                int bidx = (p * 4 + qq) * 3;
#pragma unroll
                for (int j = 0; j < 3; j++)
                    top3_upd(sd[bidx + j], si[bidx + j], m1, m2, m3, i1, i2, i3);
            }
            // x row from gmem (exact fp32; L2-hot)
            const float* xp = x + (size_t)b * CDIM * HWDIM + hwb + p;
            float xr[CDIM];
#pragma unroll
            for (int c = 0; c < CDIM; c++) xr[c] = xp[(size_t)c * HWDIM];

            float bd = 3.4e38f;
            int   bk = 1 << 30;
            int cand[3] = {i1, i2, i3};
#pragma unroll
            for (int r = 0; r < 3; r++) {
                int k = cand[r];
                const float4* er = reinterpret_cast<const float4*>(E + (k << 6));
                float q0 = 0.f, q1 = 0.f, q2 = 0.f, q3 = 0.f;
#pragma unroll
                for (int i = 0; i < 16; i++) {
                    float4 ev = er[i];
                    q0 = fmaf(xr[4*i+0], ev.x, q0);
                    q1 = fmaf(xr[4*i+1], ev.y, q1);
                    q2 = fmaf(xr[4*i+2], ev.z, q2);
                    q3 = fmaf(xr[4*i+3], ev.w, q3);
                }
                float dot = (q0 + q1) + (q2 + q3);
                float d   = fmaf(-2.f, dot, snorm[k]);
                if (d < bd || (d == bd && k < bk)) { bd = d; bk = k; }
            }
            loss_acc += bd;                       // + Σx² added globally
            sbk[p] = bk;
            atomicAdd(&shist[bk], 1u);
            out[OFF_IDX + nb + p] = (float)bk;
        }
        __syncthreads();

        // ---- cooperative coalesced writeout of quantized rows
        {
            float* op = out + (size_t)b * CDIM * HWDIM + hwb;
            int bk = sbk[pw];
            const float4* er = reinterpret_cast<const float4*>(E + (bk << 6));
#pragma unroll
            for (int ii = 0; ii < 2; ii++) {
                float4 v = er[(cgi << 1) + ii];
                int c = (cgi << 3) + (ii << 2);
                op[(size_t)(c + 0) * HWDIM + pw] = v.x;
                op[(size_t)(c + 1) * HWDIM + pw] = v.y;
                op[(size_t)(c + 2) * HWDIM + pw] = v.z;
                op[(size_t)(c + 3) * HWDIM + pw] = v.w;
            }
        }
        // next-tile A staging is separated from this tile's A reads by the
        // sd-write barrier; sbk rewrites are two barriers away.
    }

    // ---- block reductions -> globals
    float tot = loss_acc + xsq_acc;
#pragma unroll
    for (int off = 16; off; off >>= 1)
        tot += __shfl_xor_sync(0xFFFFFFFFu, tot, off);
    if (lane == 0) wsum[wid] = tot;
    __syncthreads();

    atomicAdd(&g_hist[tid], shist[tid]);
    if (tid == 0) {
        float bsum = 0.f;
#pragma unroll
        for (int i = 0; i < 16; i++) bsum += wsum[i];
        atomicAdd(&g_loss, bsum);
    }
}

// ---------------------------------------------------------------------------
// finalize: perplexity + loss + active_codes; re-zero accumulators for the
// next graph replay.
// ---------------------------------------------------------------------------
__global__ void vq_finalize(const float* __restrict__ w, float* __restrict__ out) {
    __shared__ float s_ent[16];
    __shared__ float s_act[16];
    int t = threadIdx.x;

    float pr  = (float)g_hist[t] * (1.0f / (float)NTOT);
    float ent = pr * logf(pr + 1e-10f);
    float act = (w[t] >= 0.01f) ? 1.f : 0.f;

#pragma unroll
    for (int off = 16; off; off >>= 1) {
        ent += __shfl_xor_sync(0xFFFFFFFFu, ent, off);
        act += __shfl_xor_sync(0xFFFFFFFFu, act, off);
    }
    if ((t & 31) == 0) { s_ent[t >> 5] = ent; s_act[t >> 5] = act; }
    __syncthreads();
    if (t == 0) {
        float esum = 0.f, asum = 0.f;
#pragma unroll
        for (int i = 0; i < 16; i++) { esum += s_ent[i]; asum += s_act[i]; }
        out[OFF_LOSS] = g_loss * (1.0f / ((float)NTOT * (float)CDIM));
        out[OFF_PERP] = expf(-esum);
        out[OFF_ACT]  = asum;
    }
    __syncthreads();
    g_hist[t] = 0u;
    if (t == 0) g_loss = 0.f;
}

// ---------------------------------------------------------------------------
extern "C" void kernel_launch(void* const* d_in, const int* in_sizes, int n_in,
                              void* d_out, int out_size) {
    const float* x = (const float*)d_in[0];   // [16,64,64,64]
    const float* E = (const float*)d_in[1];   // [512,64]
    const float* w = (const float*)d_in[2];   // [512]
    float* out = (float*)d_out;

    cudaFuncSetAttribute(vq_main, cudaFuncAttributeMaxDynamicSharedMemorySize,
                         SMEM_BYTES);

    vq_main<<<GRID, TPB, SMEM_BYTES>>>(x, E, out);
    vq_finalize<<<1, KCB>>>(w, out);
}

// round 10
// speedup vs baseline: 3.4377x; 1.2798x over previous
#include <cuda_runtime.h>
#include <cuda_bf16.h>
#include <cstdint>

// Problem constants
#define NB      16
#define CDIM    64
#define HWDIM   4096
#define NTOT    65536
#define KCB     512
#define OUT_Q   4194304
#define OFF_LOSS (OUT_Q)
#define OFF_PERP (OUT_Q + 1)
#define OFF_ACT  (OUT_Q + 2)
#define OFF_IDX  (OUT_Q + 3)

#define TPB     512
#define GRID    148
#define TILEP   64
#define NTILES  (NTOT / TILEP)      // 1024 -> 6.92/CTA -> 0.988 balance

// smem rows padded to 72 halves (144B = 36 banks) -> ldmatrix conflict-free
#define ROWB    144
// ---- dynamic smem byte offsets ----
#define SO_BHI   0                  // E_hi bf16 [512][72h]  = 73728
#define SO_BLO   73728              // E_lo                  = 73728
#define SO_AHI   147456             // X_hi bf16 [64][72h]   =  9216
#define SO_ALO   156672             // X_lo                  =  9216
#define SO_XF    165888             // X fp32 [64][68]       = 17408
#define SO_SNORM 183296             // 512 f
#define SO_H     185344             // 512 f (= norm/2)
#define SO_SD    187392             // float [64][4][2]      =  2048
#define SO_SI    189440             // int   [64][4][2]      =  2048
#define SO_HIST  191488             // 512 u32
#define SO_SBK   193536             // 64 int
#define SO_WSUM  193792             // 16 f
#define SMEM_BYTES 193856

__device__ float        g_loss;
__device__ unsigned int g_hist[KCB];

// ---------------- family-portable tensor helpers (sm_80+ PTX only) --------
__device__ __forceinline__ void mma16816(float* d, const uint32_t* a,
                                         const uint32_t* b) {
    asm volatile(
        "mma.sync.aligned.m16n8k16.row.col.f32.bf16.bf16.f32 "
        "{%0,%1,%2,%3}, {%4,%5,%6,%7}, {%8,%9}, {%0,%1,%2,%3};"
        : "+f"(d[0]), "+f"(d[1]), "+f"(d[2]), "+f"(d[3])
        : "r"(a[0]), "r"(a[1]), "r"(a[2]), "r"(a[3]), "r"(b[0]), "r"(b[1]));
}
__device__ __forceinline__ void ldsm4(uint32_t* r, uint32_t addr) {
    asm volatile("ldmatrix.sync.aligned.m8n8.x4.shared.b16 {%0,%1,%2,%3}, [%4];"
                 : "=r"(r[0]), "=r"(r[1]), "=r"(r[2]), "=r"(r[3]) : "r"(addr));
}
__device__ __forceinline__ void pack_hilo(float f0, float f1,
                                          uint32_t& whi, uint32_t& wlo) {
    __nv_bfloat16 h0 = __float2bfloat16_rn(f0);
    __nv_bfloat16 h1 = __float2bfloat16_rn(f1);
    float r0 = f0 - __bfloat162float(h0);
    float r1 = f1 - __bfloat162float(h1);
    __nv_bfloat16 l0 = __float2bfloat16_rn(r0);
    __nv_bfloat16 l1 = __float2bfloat16_rn(r1);
    whi = (uint32_t)__bfloat16_as_ushort(h0) | ((uint32_t)__bfloat16_as_ushort(h1) << 16);
    wlo = (uint32_t)__bfloat16_as_ushort(l0) | ((uint32_t)__bfloat16_as_ushort(l1) << 16);
}
__device__ __forceinline__ void top2_upd(float m, int k,
                                         float& b1, float& b2, int& k1, int& k2) {
    if (m > b2) {
        if (m > b1) { b2 = b1; k2 = k1; b1 = m; k1 = k; }
        else        { b2 = m;  k2 = k; }
    }
}
__device__ __forceinline__ void top3_upd(float m, int k,
                                         float& b1, float& b2, float& b3,
                                         int& k1, int& k2, int& k3) {
    if (m > b3) {
        if (m > b2) {
            b3 = b2; k3 = k2;
            if (m > b1) { b2 = b1; k2 = k1; b1 = m; k1 = k; }
            else        { b2 = m;  k2 = k; }
        } else { b3 = m; k3 = k; }
    }
}

// ---------------------------------------------------------------------------
extern __shared__ char sm[];

__global__ __launch_bounds__(TPB, 1)
void vq_main(const float* __restrict__ x,
             const float* __restrict__ E,
             float* __restrict__ out) {
    float*        sxf   = (float*)(sm + SO_XF);
    float*        snorm = (float*)(sm + SO_SNORM);
    float*        hh    = (float*)(sm + SO_H);
    float*        sd    = (float*)(sm + SO_SD);
    int*          si    = (int*)(sm + SO_SI);
    unsigned int* shist = (unsigned int*)(sm + SO_HIST);
    int*          sbk   = (int*)(sm + SO_SBK);
    float*        wsum  = (float*)(sm + SO_WSUM);

    const int tid  = threadIdx.x;
    const int wid  = tid >> 5;
    const int lane = tid & 31;

    // ---- one-time: codebook -> bf16 hi/lo (padded rows) + norms
    {
        const int k = tid;
        const float4* er = reinterpret_cast<const float4*>(E + (k << 6));
        char* bh = sm + SO_BHI + k * ROWB;
        char* bl = sm + SO_BLO + k * ROWB;
        float s = 0.f;
#pragma unroll
        for (int i = 0; i < 16; i++) {
            float4 v = er[i];
            s = fmaf(v.x, v.x, s); s = fmaf(v.y, v.y, s);
            s = fmaf(v.z, v.z, s); s = fmaf(v.w, v.w, s);
            uint32_t whi, wlo;
            pack_hilo(v.x, v.y, whi, wlo);
            *(uint32_t*)(bh + i * 8)     = whi;
            *(uint32_t*)(bl + i * 8)     = wlo;
            pack_hilo(v.z, v.w, whi, wlo);
            *(uint32_t*)(bh + i * 8 + 4) = whi;
            *(uint32_t*)(bl + i * 8 + 4) = wlo;
        }
        snorm[k] = s;
        hh[k]    = 0.5f * s;
        shist[k] = 0u;
    }
    __syncthreads();

    const int pw  = tid & 63;     // staging/writeout point
    const int cgi = tid >> 6;     // staging/writeout channel group (0..7)
    const int rg  = wid >> 2;     // row group: points rg*16 .. +15
    const int wq  = wid & 3;      // code quarter: codes wq*128 .. +127

    // ldmatrix lane addressing
    const uint32_t smu = (uint32_t)__cvta_generic_to_shared(sm);
    const int sel = lane >> 3;
    const uint32_t aoff =
        (uint32_t)(rg * 16 + (lane & 7) + (sel & 1) * 8) * ROWB + (uint32_t)((sel >> 1) * 16);
    const uint32_t ahiA = smu + SO_AHI + aoff;
    const uint32_t aloA = smu + SO_ALO + aoff;
    // B x4: lane groups 0-7/8-15/16-23/24-31 -> k-offsets 0,16,32,48 bytes
    const uint32_t bln  = (uint32_t)((lane & 7) * ROWB + (lane >> 3) * 16);
    const uint32_t bhiB = smu + SO_BHI + bln;
    const uint32_t bloB = smu + SO_BLO + bln;

    float loss_acc = 0.f, xsq_acc = 0.f;

    for (int t = blockIdx.x; t < NTILES; t += GRID) {
        const int nb  = t << 6;
        const int b   = nb >> 12;
        const int hwb = nb & (HWDIM - 1);
        const float* xg = x + (size_t)b * CDIM * HWDIM + hwb;

        // ---- stage X tile: bf16 hi/lo (MMA) + fp32 (rescore)
#pragma unroll
        for (int jj = 0; jj < 4; jj++) {
            int c0 = (cgi << 3) + (jj << 1);
            float v0 = xg[(size_t)c0 * HWDIM + pw];
            float v1 = xg[(size_t)(c0 + 1) * HWDIM + pw];
            xsq_acc = fmaf(v0, v0, xsq_acc);
            xsq_acc = fmaf(v1, v1, xsq_acc);
            uint32_t whi, wlo;
            pack_hilo(v0, v1, whi, wlo);
            *(uint32_t*)(sm + SO_AHI + pw * ROWB + c0 * 2) = whi;
            *(uint32_t*)(sm + SO_ALO + pw * ROWB + c0 * 2) = wlo;
            sxf[pw * 68 + c0]     = v0;
            sxf[pw * 68 + c0 + 1] = v1;
        }
        __syncthreads();

        // ---- A fragments (persist across the n-loop)
        uint32_t ahi[16], alo[16];
#pragma unroll
        for (int kt = 0; kt < 4; kt++) {
            ldsm4(ahi + 4 * kt, ahiA + kt * 32);
            ldsm4(alo + 4 * kt, aloA + kt * 32);
        }

        // ---- per-lane top-2 of m = dot - ||e||^2/2 (h folded into acc init)
        float a1 = -3.4e38f, a2 = -3.4e38f;      // row rg*16 + (lane>>2)
        float c1 = -3.4e38f, c2 = -3.4e38f;      // row +8
        int ka1 = 0, ka2 = 0, kc1 = 0, kc2 = 0;

        const uint32_t nqbase = (uint32_t)(wq * 128) * ROWB;
#pragma unroll 2
        for (int nt = 0; nt < 16; nt++) {
            const uint32_t nbyt = nqbase + (uint32_t)(nt * 8) * ROWB;
            const int c0 = wq * 128 + nt * 8 + 2 * (lane & 3);
            float2 hp = *(const float2*)(hh + c0);
            float acc1[4] = {-hp.x, -hp.y, -hp.x, -hp.y};   // h folded in
            float acc2[4] = {0.f, 0.f, 0.f, 0.f};
            uint32_t bh[8], bl[8];
            ldsm4(bh,     bhiB + nbyt);
            ldsm4(bh + 4, bhiB + nbyt + 64);
            ldsm4(bl,     bloB + nbyt);
            ldsm4(bl + 4, bloB + nbyt + 64);
#pragma unroll
            for (int kt = 0; kt < 4; kt++) {
                mma16816(acc1, ahi + 4 * kt, bh + 2 * kt);  // hi*hi
                mma16816(acc2, alo + 4 * kt, bh + 2 * kt);  // lo*hi
                mma16816(acc1, ahi + 4 * kt, bl + 2 * kt);  // hi*lo
            }
            top2_upd(acc1[0] + acc2[0], c0,     a1, a2, ka1, ka2);
            top2_upd(acc1[1] + acc2[1], c0 + 1, a1, a2, ka1, ka2);
            top2_upd(acc1[2] + acc2[2], c0,     c1, c2, kc1, kc2);
            top2_upd(acc1[3] + acc2[3], c0 + 1, c1, c2, kc1, kc2);
        }

        // ---- merge across the 4 lanes sharing each row (bfly 1,2)
#pragma unroll
        for (int off = 1; off <= 2; off <<= 1) {
            float o1 = __shfl_xor_sync(0xFFFFFFFFu, a1, off);
            float o2 = __shfl_xor_sync(0xFFFFFFFFu, a2, off);
            int   p1 = __shfl_xor_sync(0xFFFFFFFFu, ka1, off);
            int   p2 = __shfl_xor_sync(0xFFFFFFFFu, ka2, off);
            top2_upd(o1, p1, a1, a2, ka1, ka2);
            top2_upd(o2, p2, a1, a2, ka1, ka2);
            o1 = __shfl_xor_sync(0xFFFFFFFFu, c1, off);
            o2 = __shfl_xor_sync(0xFFFFFFFFu, c2, off);
            p1 = __shfl_xor_sync(0xFFFFFFFFu, kc1, off);
            p2 = __shfl_xor_sync(0xFFFFFFFFu, kc2, off);
            top2_upd(o1, p1, c1, c2, kc1, kc2);
            top2_upd(o2, p2, c1, c2, kc1, kc2);
        }
        if ((lane & 3) == 0) {
            int ra = rg * 16 + (lane >> 2);
            int rb = ra + 8;
            int ba = (ra * 4 + wq) * 2;
            int bb = (rb * 4 + wq) * 2;
            sd[ba] = a1; sd[ba + 1] = a2;
            si[ba] = ka1; si[ba + 1] = ka2;
            sd[bb] = c1; sd[bb + 1] = c2;
            si[bb] = kc1; si[bb + 1] = kc2;
        }
        __syncthreads();

        // ---- merge 8 candidates -> top3 -> EXACT fp32 rescore (R1 order,
        //      x from smem; all 512 threads? one thread per point)
        if (tid < TILEP) {
            const int p = tid;
            float m1 = -3.4e38f, m2 = -3.4e38f, m3 = -3.4e38f;
            int   i1 = 0, i2 = 0, i3 = 0;
#pragma unroll
            for (int qq = 0; qq < 4; qq++) {
                int bidx = (p * 4 + qq) * 2;
                top3_upd(sd[bidx],     si[bidx],     m1, m2, m3, i1, i2, i3);
                top3_upd(sd[bidx + 1], si[bidx + 1], m1, m2, m3, i1, i2, i3);
            }
            const float4* xr4 = reinterpret_cast<const float4*>(sxf + p * 68);
            float bd = 3.4e38f;
            int   bk = 1 << 30;
            int cand[3] = {i1, i2, i3};
#pragma unroll
            for (int r = 0; r < 3; r++) {
                int k = cand[r];
                const float4* er = reinterpret_cast<const float4*>(E + (k << 6));
                float q0 = 0.f, q1 = 0.f, q2 = 0.f, q3 = 0.f;
#pragma unroll
                for (int i = 0; i < 16; i++) {
                    float4 xv = xr4[i];
                    float4 ev = er[i];
                    q0 = fmaf(xv.x, ev.x, q0);
                    q1 = fmaf(xv.y, ev.y, q1);
                    q2 = fmaf(xv.z, ev.z, q2);
                    q3 = fmaf(xv.w, ev.w, q3);
                }
                float dot = (q0 + q1) + (q2 + q3);
                float d   = fmaf(-2.f, dot, snorm[k]);
                if (d < bd || (d == bd && k < bk)) { bd = d; bk = k; }
            }
            loss_acc += bd;                       // + Σx² added globally
            sbk[p] = bk;
            atomicAdd(&shist[bk], 1u);
            out[OFF_IDX + nb + p] = (float)bk;
        }
        __syncthreads();

        // ---- cooperative coalesced writeout of quantized rows
        {
            float* op = out + (size_t)b * CDIM * HWDIM + hwb;
            int bk = sbk[pw];
            const float4* er = reinterpret_cast<const float4*>(E + (bk << 6));
#pragma unroll
            for (int ii = 0; ii < 2; ii++) {
                float4 v = er[(cgi << 1) + ii];
                int c = (cgi << 3) + (ii << 2);
                op[(size_t)(c + 0) * HWDIM + pw] = v.x;
                op[(size_t)(c + 1) * HWDIM + pw] = v.y;
                op[(size_t)(c + 2) * HWDIM + pw] = v.z;
                op[(size_t)(c + 3) * HWDIM + pw] = v.w;
            }
        }
    }

    // ---- block reductions -> globals
    float tot = loss_acc + xsq_acc;
#pragma unroll
    for (int off = 16; off; off >>= 1)
        tot += __shfl_xor_sync(0xFFFFFFFFu, tot, off);
    if (lane == 0) wsum[wid] = tot;
    __syncthreads();

    atomicAdd(&g_hist[tid], shist[tid]);
    if (tid == 0) {
        float bsum = 0.f;
#pragma unroll
        for (int i = 0; i < 16; i++) bsum += wsum[i];
        atomicAdd(&g_loss, bsum);
    }
}

// ---------------------------------------------------------------------------
// finalize: perplexity + loss + active_codes; re-zero accumulators for the
// next graph replay.
// ---------------------------------------------------------------------------
__global__ void vq_finalize(const float* __restrict__ w, float* __restrict__ out) {
    __shared__ float s_ent[16];
    __shared__ float s_act[16];
    int t = threadIdx.x;

    float pr  = (float)g_hist[t] * (1.0f / (float)NTOT);
    float ent = pr * logf(pr + 1e-10f);
    float act = (w[t] >= 0.01f) ? 1.f : 0.f;

#pragma unroll
    for (int off = 16; off; off >>= 1) {
        ent += __shfl_xor_sync(0xFFFFFFFFu, ent, off);
        act += __shfl_xor_sync(0xFFFFFFFFu, act, off);
    }
    if ((t & 31) == 0) { s_ent[t >> 5] = ent; s_act[t >> 5] = act; }
    __syncthreads();
    if (t == 0) {
        float esum = 0.f, asum = 0.f;
#pragma unroll
        for (int i = 0; i < 16; i++) { esum += s_ent[i]; asum += s_act[i]; }
        out[OFF_LOSS] = g_loss * (1.0f / ((float)NTOT * (float)CDIM));
        out[OFF_PERP] = expf(-esum);
        out[OFF_ACT]  = asum;
    }
    __syncthreads();
    g_hist[t] = 0u;
    if (t == 0) g_loss = 0.f;
}

// ---------------------------------------------------------------------------
extern "C" void kernel_launch(void* const* d_in, const int* in_sizes, int n_in,
                              void* d_out, int out_size) {
    const float* x = (const float*)d_in[0];   // [16,64,64,64]
    const float* E = (const float*)d_in[1];   // [512,64]
    const float* w = (const float*)d_in[2];   // [512]
    float* out = (float*)d_out;

    cudaFuncSetAttribute(vq_main, cudaFuncAttributeMaxDynamicSharedMemorySize,
                         SMEM_BYTES);

    vq_main<<<GRID, TPB, SMEM_BYTES>>>(x, E, out);
    vq_finalize<<<1, KCB>>>(w, out);
}